// round 15
// baseline (speedup 1.0000x reference)
#include <cuda_runtime.h>
#include <cstdint>

// DeNuCLoss: top-4 matching loss, single persistent kernel, software grid
// barriers. 512 co-resident blocks (4/SM guaranteed via launch_bounds).
// cost = 0.1*dist(q,g) - p_label(q) >= -key (key = p0 if all labels 0, else
// max(p0,p1)). Queries bucket-sorted by descending key; each gt (split 4 ways
// across lanes) scans until suffix-min(-key) > its 4th-best cost.
// Phases: A softmax+smem-hist+compact | B bases | C 2-pass scatter | D top-4
// (1024 slots/batch) | E output+cleanup.

#define BS 8
#define NQ 16384
#define NG 1024
#define NBINS 256
#define NCHUNK 512                 // NQ/32
#define NBLOCKS 512
#define NTHREADS 256

__device__ float4   g_sq[BS * NQ];        // sorted: x, y, -p0, idx(bits)
__device__ float    g_sp1[BS * NQ];       // sorted: -p1 (only if labels mixed)
__device__ int      g_match[BS * NQ];     // zero-init; reset in-kernel each run
__device__ unsigned g_hist[BS * NBINS];   // zero-init; reset at end each run
__device__ unsigned g_cursor[BS * NBINS];
__device__ unsigned g_chunkU[BS * NCHUNK];// zero-init; reset at end each run
__device__ int      g_valid_list[BS][NG];
__device__ int      g_valid_cnt[BS];
__device__ int      g_lab_nz[BS];         // strict: any VALID gt w/ label!=0
__device__ int      g_mask_kind;
__device__ float    g_cls1, g_cls2, g_reg;  // zero-init; reset at end each run
__device__ unsigned g_bar_arrive, g_bar_gen;

__device__ __forceinline__ float fast_sqrtf(float x) {
    float r;
    asm("sqrt.approx.f32 %0, %1;" : "=f"(r) : "f"(x));
    return r;
}

// jax top_k total order: smaller cost wins; exact tie -> smaller query index.
__device__ __forceinline__ bool better(float va, int ia, float vb, int ib) {
    return (va < vb) || (va == vb && ia < ib);
}

__device__ __forceinline__ void grid_barrier() {
    __syncthreads();
    if (threadIdx.x == 0) {
        unsigned gen = atomicAdd(&g_bar_gen, 0u);   // read BEFORE arriving
        __threadfence();
        if (atomicAdd(&g_bar_arrive, 1u) == NBLOCKS - 1) {
            atomicExch(&g_bar_arrive, 0u);
            __threadfence();
            atomicAdd(&g_bar_gen, 1u);
        } else {
            while (atomicAdd(&g_bar_gen, 0u) == gen) __nanosleep(64);
        }
    }
    __syncthreads();
}

__device__ __forceinline__ float block_reduce_256(float v) {
    __shared__ float ws[8];
    __syncthreads();                        // protect ws across repeated calls
#pragma unroll
    for (int off = 16; off; off >>= 1) v += __shfl_xor_sync(0xffffffffu, v, off);
    if ((threadIdx.x & 31) == 0) ws[threadIdx.x >> 5] = v;
    __syncthreads();
    float t = 0.0f;
    if (threadIdx.x < 8) {
        t = ws[threadIdx.x];
#pragma unroll
        for (int off = 4; off; off >>= 1) t += __shfl_xor_sync(0xffu, t, off);
    }
    return t;   // valid in thread 0
}

// Identical code in phases A and C -> identical bins (required for scatter).
struct QP { float p0, p1, nll1, key; int bin; };
__device__ __forceinline__ QP qprob(const float* __restrict__ pl, int i, int lab) {
    float l0 = pl[2 * i], l1 = pl[2 * i + 1];
    float m  = fmaxf(l0, l1);
    float e0 = __expf(l0 - m), e1 = __expf(l1 - m);
    float sum = e0 + e1, inv = 1.0f / sum;
    QP r;
    r.p0 = e0 * inv; r.p1 = e1 * inv;
    r.nll1 = m + __logf(sum) - l1;
    r.key = lab ? fmaxf(r.p0, r.p1) : r.p0;   // lower bound on p_label
    r.bin = min(NBINS - 1, (int)(r.key * 256.0f));
    return r;
}

#define CEX3(va, ia, sa, vb, ib, sb)                                   \
    if (better(vb, ib, va, ia)) {                                      \
        float tv = va; va = vb; vb = tv;                               \
        int ti = ia; ia = ib; ib = ti;                                 \
        int ts = sa; sa = sb; sb = ts;                                 \
    }

#define INS(cst, qi, ps)                                                      \
    if (better(cst, qi, v3, i3)) {                                            \
        if (better(cst, qi, v1, i1)) {                                        \
            v3 = v2; i3 = i2; s3 = s2; v2 = v1; i2 = i1; s2 = s1;             \
            if (better(cst, qi, v0, i0)) {                                    \
                v1 = v0; i1 = i0; s1 = s0; v0 = cst; i0 = qi; s0 = ps;        \
            } else { v1 = cst; i1 = qi; s1 = ps; }                            \
        } else if (better(cst, qi, v2, i2)) {                                 \
            v3 = v2; i3 = i2; s3 = s2; v2 = cst; i2 = qi; s2 = ps;            \
        } else { v3 = cst; i3 = qi; s3 = ps; }                                \
    }

__global__ __launch_bounds__(NTHREADS, 4) void k_all(
    const float* __restrict__ pc, const float* __restrict__ pl,
    const float* __restrict__ gtc, const int* __restrict__ gtl,
    const unsigned char* __restrict__ gmsk, float* __restrict__ out)
{
    __shared__ union { unsigned u[NBINS]; float f[NCHUNK]; } sm;
    __shared__ unsigned h2[NBINS];     // block scatter bases (phase C)
    __shared__ int slabA;              // own batch "any label != 0" (loose)
    const int tid  = threadIdx.x;
    const int blkbase = blockIdx.x * NTHREADS;  // 1 item/thread
    const int bA = blockIdx.x >> 6;             // 64 blocks per batch
    const int iA = blkbase + tid;               // this thread's item
    const float PINF = __int_as_float(0x7f800000);
    const float NINF = __int_as_float(0xff800000);

    // Loose label flag for OWN batch only (4 loads/thread).
    if (tid == 0) slabA = 0;
    __syncthreads();
#pragma unroll
    for (int k = 0; k < 4; k++)
        if (gtl[bA * NG + tid + k * 256] != 0) slabA = 1;  // benign race
    __syncthreads();

    // ================= Phase A: compact (block 0) + softmax/smem-hist =======
    if (blockIdx.x == 0) {
        if (tid == 0) {
            bool any_mis = false, b1nz = false, any3f = false;
            for (int t = 0; t < 256; t++) {
                unsigned char v = gmsk[t];
                if ((t & 3) != 0 && v) {
                    any_mis = true;
                    if ((t & 3) == 1) b1nz = true;
                    if (v == 0x3F) any3f = true;
                }
            }
            g_mask_kind = !any_mis ? 0 : ((!b1nz && any3f) ? 2 : 1);
        }
        __syncthreads();
        int b = tid >> 5, lane = tid & 31, kind = g_mask_kind;
        int cnt = 0, labnz = 0;
        for (int j = 0; j < NG; j += 32) {
            int g = j + lane, i = b * NG + g;
            bool mk;
            if (kind == 0)      mk = ((const int*)gmsk)[i] != 0;
            else if (kind == 1) mk = gmsk[i] != 0;
            else                mk = ((const float*)gmsk)[i] != 0.0f;
            unsigned bal = __ballot_sync(0xffffffffu, mk);
            if (mk) {
                int pos = cnt + __popc(bal & ((1u << lane) - 1u));
                g_valid_list[b][pos] = g;
                if (gtl[i] != 0) labnz = 1;
            }
            cnt += __popc(bal);
        }
        unsigned lb = __ballot_sync(0xffffffffu, labnz);
        if (lane == 0) { g_valid_cnt[b] = cnt; g_lab_nz[b] = (lb != 0); }
    }
    sm.u[tid] = 0u;
    __syncthreads();
    float cls1;
    {
        QP q = qprob(pl, iA, slabA);
        atomicAdd(&sm.u[q.bin], 1u);          // smem histogram
        cls1 = q.nll1;
    }
    __syncthreads();
    if (sm.u[tid]) atomicAdd(&g_hist[bA * NBINS + tid], sm.u[tid]);
    {
        float p = block_reduce_256(cls1);
        if (tid == 0) atomicAdd(&g_cls1, p);
    }
    grid_barrier();

    // ================= Phase B: descending-bin bases ========================
    if (blockIdx.x < BS) {
        int b = blockIdx.x;
        unsigned h0 = g_hist[b * NBINS + tid];
        sm.u[tid] = h0;
        __syncthreads();
        for (int off = 1; off < NBINS; off <<= 1) {
            unsigned v = (tid + off < NBINS) ? sm.u[tid + off] : 0u;
            __syncthreads();
            sm.u[tid] += v;
            __syncthreads();
        }
        g_cursor[b * NBINS + tid] = sm.u[tid] - h0;  // count of bins above
    }
    grid_barrier();

    // ================= Phase C: two-pass block scatter ======================
    {
        int labS = g_lab_nz[bA];
        QP q = qprob(pl, iA, slabA);
        float x = pc[2 * iA], y = pc[2 * iA + 1];
        sm.u[tid] = 0u;
        __syncthreads();
        atomicAdd(&sm.u[q.bin], 1u);
        __syncthreads();
        unsigned cb_ = sm.u[tid];
        h2[tid] = cb_ ? atomicAdd(&g_cursor[bA * NBINS + tid], cb_) : 0u;
        __syncthreads();
        sm.u[tid] = 0u;
        __syncthreads();
        int qi = iA & (NQ - 1);
        unsigned r = atomicAdd(&sm.u[q.bin], 1u);
        unsigned pos = h2[q.bin] + r;
        g_sq[bA * NQ + pos] = make_float4(x, y, -q.p0, __int_as_float(qi));
        // raw-uint max == float min (keys strictly negative)
        atomicMax(&g_chunkU[bA * NCHUNK + (pos >> 5)], __float_as_uint(-q.key));
        if (labS) g_sp1[bA * NQ + pos] = -q.p1;
    }
    grid_barrier();

    // ================= Phase D: split top-4 per gt ==========================
    // block = (batch[3b], part[6b]); parts 0..15 cover 1024 slots/batch,
    // parts >=16 skip uniformly. Lane = gt(8) x split(4).
    float v0 = PINF, v1 = PINF, v2 = PINF, v3 = NINF;
    int i0 = 0x7fffffff, i1 = 0x7fffffff, i2 = 0x7fffffff, i3 = 0x7fffffff;
    int s0 = 0, s1 = 0, s2 = 0, s3 = 0;
    bool leader = false;
    int bD = blockIdx.x >> 6;
    float gx = 0.0f, gy = 0.0f;

    {
        int part = blockIdx.x & 63;
        int cnt = g_valid_cnt[bD];
        if (part * 64 < cnt) {                     // block-uniform
            sm.f[tid]       = __uint_as_float(g_chunkU[bD * NCHUNK + tid]);
            sm.f[tid + 256] = __uint_as_float(g_chunkU[bD * NCHUNK + tid + 256]);
            __syncthreads();
            for (int off = 1; off < NCHUNK; off <<= 1) {
                float a  = (tid + off < NCHUNK) ? sm.f[tid + off] : PINF;
                float b2 = (tid + 256 + off < NCHUNK) ? sm.f[tid + 256 + off] : PINF;
                __syncthreads();
                sm.f[tid]       = fminf(sm.f[tid], a);
                sm.f[tid + 256] = fminf(sm.f[tid + 256], b2);
                __syncthreads();
            }

            int w = tid >> 5, lane = tid & 31;
            int g = lane >> 2, s = lane & 3;
            int slot = part * 64 + w * 8 + g;
            bool act = slot < cnt;
            leader = act && (s == 0);
            int gi = g_valid_list[bD][act ? slot : 0];
            gx = gtc[(bD * NG + gi) * 2];
            gy = gtc[(bD * NG + gi) * 2 + 1];
            bool lab0 = (gtl[bD * NG + gi] == 0);
            if (act) v3 = PINF;                     // inactive: v3=-inf -> break

            const float4* __restrict__ qb = g_sq + bD * NQ;
            if (!g_lab_nz[bD]) {
                for (int c = s; c < NCHUNK; c += 4) {
                    if (sm.f[c] > v3) break;
                    int cb = c * 32;
#pragma unroll 4
                    for (int jj = 0; jj < 32; jj++) {
                        float4 q = qb[cb + jj];
                        float dx = q.x - gx, dy = q.y - gy;
                        float cst = fmaf(0.1f, fast_sqrtf(fmaf(dx, dx, dy * dy)), q.z);
                        if (cst <= v3) { int qi = __float_as_int(q.w); int ps = cb + jj; INS(cst, qi, ps); }
                    }
                }
            } else {
                const float* __restrict__ z1 = g_sp1 + bD * NQ;
                for (int c = s; c < NCHUNK; c += 4) {
                    if (sm.f[c] > v3) break;
                    int cb = c * 32;
                    for (int jj = 0; jj < 32; jj++) {
                        float4 q = qb[cb + jj];
                        float zc = lab0 ? q.z : z1[cb + jj];
                        float dx = q.x - gx, dy = q.y - gy;
                        float cst = fmaf(0.1f, fast_sqrtf(fmaf(dx, dx, dy * dy)), zc);
                        if (cst <= v3) { int qi = __float_as_int(q.w); int ps = cb + jj; INS(cst, qi, ps); }
                    }
                }
            }

            // Merge the 4 disjoint split lists per gt (xor 2, then 1).
#pragma unroll
            for (int off = 2; off >= 1; off >>= 1) {
                float w0 = __shfl_xor_sync(0xffffffffu, v0, off);
                float w1 = __shfl_xor_sync(0xffffffffu, v1, off);
                float w2 = __shfl_xor_sync(0xffffffffu, v2, off);
                float w3 = __shfl_xor_sync(0xffffffffu, v3, off);
                int j0 = __shfl_xor_sync(0xffffffffu, i0, off);
                int j1 = __shfl_xor_sync(0xffffffffu, i1, off);
                int j2 = __shfl_xor_sync(0xffffffffu, i2, off);
                int j3 = __shfl_xor_sync(0xffffffffu, i3, off);
                int t0 = __shfl_xor_sync(0xffffffffu, s0, off);
                int t1 = __shfl_xor_sync(0xffffffffu, s1, off);
                int t2 = __shfl_xor_sync(0xffffffffu, s2, off);
                int t3 = __shfl_xor_sync(0xffffffffu, s3, off);
                // lower half of bitonic merge-8
                if (better(w3, j3, v0, i0)) { v0 = w3; i0 = j3; s0 = t3; }
                if (better(w2, j2, v1, i1)) { v1 = w2; i1 = j2; s1 = t2; }
                if (better(w1, j1, v2, i2)) { v2 = w1; i2 = j1; s2 = t1; }
                if (better(w0, j0, v3, i3)) { v3 = w0; i3 = j0; s3 = t0; }
                // cleanup sort-4
                CEX3(v0, i0, s0, v2, i2, s2);
                CEX3(v1, i1, s1, v3, i3, s3);
                CEX3(v0, i0, s0, v1, i1, s1);
                CEX3(v2, i2, s2, v3, i3, s3);
            }
        }
    }

    // Epilogue: reg partial + match flags + cls correction (leaders only).
    float regs_ = 0.0f, corr = 0.0f;
    if (leader) {
        int ps4[4] = {s0, s1, s2, s3};
        int ii4[4] = {i0, i1, i2, i3};
        const float4* __restrict__ qb = g_sq + bD * NQ;
#pragma unroll
        for (int k = 0; k < 4; k++) {
            float4 q = qb[ps4[k]];
            float dx = q.x - gx, dy = q.y - gy;
            regs_ += dx * dx + dy * dy;
            int gidx = bD * NQ + ii4[k];
            if (atomicExch(&g_match[gidx], 1) == 0)   // first matcher pays corr
                corr += pl[2 * gidx + 1] - pl[2 * gidx];
        }
    }
    {
        float rsum = block_reduce_256(regs_);
        float csum = block_reduce_256(corr);
        if (tid == 0) {
            if (rsum != 0.0f) atomicAdd(&g_reg, rsum);
            if (csum != 0.0f) atomicAdd(&g_cls2, csum);
        }
    }
    grid_barrier();

    // ================= Phase E: output + cleanup for next replay ============
    if (leader) {                       // reset exactly the flags we set
        g_match[bD * NQ + i0] = 0;
        g_match[bD * NQ + i1] = 0;
        g_match[bD * NQ + i2] = 0;
        g_match[bD * NQ + i3] = 0;
    }
    if (blockIdx.x == 128)
        for (int j = tid; j < BS * NBINS; j += NTHREADS) g_hist[j] = 0u;
    if (blockIdx.x == 129)
        for (int j = tid; j < BS * NCHUNK; j += NTHREADS) g_chunkU[j] = 0u;
    if (blockIdx.x == 130 && tid == 0) {
        float R = atomicAdd(&g_reg, 0.0f);
        float A = atomicAdd(&g_cls1, 0.0f) + atomicAdd(&g_cls2, 0.0f);
        int n = 0;
#pragma unroll
        for (int b = 0; b < BS; b++) n += g_valid_cnt[b];
        float denom = 8.0f * (float)(n > 0 ? n : 1);   // n_valid*TOP_K*2
        out[0] = 5.0f * R / denom;
        out[1] = A / (float)(BS * NQ);
        g_reg = 0.0f; g_cls1 = 0.0f; g_cls2 = 0.0f;
    }
}

extern "C" void kernel_launch(void* const* d_in, const int* in_sizes, int n_in,
                              void* d_out, int out_size) {
    const float* pc   = (const float*)d_in[0];   // pred_coords (8,16384,2)
    const float* pl   = (const float*)d_in[1];   // pred_logits (8,16384,2)
    const float* gtc  = (const float*)d_in[2];   // gt_coords   (8,1024,2)
    const int*   gtl  = (const int*)d_in[3];     // gt_labels   (8,1024)
    const unsigned char* gmsk = (const unsigned char*)d_in[4];  // gt_masks

    k_all<<<NBLOCKS, NTHREADS>>>(pc, pl, gtc, gtl, gmsk, (float*)d_out);
}

// round 17
// speedup vs baseline: 1.0356x; 1.0356x over previous
#include <cuda_runtime.h>
#include <cstdint>

// DeNuCLoss: top-4 matching loss, single persistent kernel, TWO software grid
// barriers (volatile-load polling) + last-block-out completion.
// cost = 0.1*dist(q,g) - p_label(q) >= -key (key = p0 if all labels 0, else
// max(p0,p1)). Queries bucket-sorted by descending key; each gt (split 4 ways
// across lanes) scans until suffix-min(-key) > its 4th-best cost.
// Phases: A softmax+smem-hist+compact | bar | C bases(redundant)+2-pass scatter
// | bar | D top-4 + losses | fence+done-counter: last block outputs + resets.

#define BS 8
#define NQ 16384
#define NG 1024
#define NBINS 256
#define NCHUNK 512                 // NQ/32
#define NBLOCKS 512
#define NTHREADS 256

__device__ float4   g_sq[BS * NQ];        // sorted: x, y, -p0, idx(bits)
__device__ float    g_sp1[BS * NQ];       // sorted: -p1 (only if labels mixed)
__device__ unsigned g_match[BS * NQ];     // gen-tagged; NO reset needed
__device__ unsigned g_hist[BS * NBINS];   // zero-init; reset by last block
__device__ unsigned g_cursor[BS * NBINS]; // within-bin claim; reset by last blk
__device__ unsigned g_chunkU[BS * NCHUNK];// zero-init; reset by last block
__device__ int      g_valid_list[BS][NG];
__device__ int      g_valid_cnt[BS];
__device__ int      g_lab_nz[BS];         // strict: any VALID gt w/ label!=0
__device__ int      g_mask_kind;
__device__ float    g_cls1, g_cls2, g_reg;  // reset by last block
__device__ unsigned g_bar_arrive, g_bar_gen, g_done;

__device__ __forceinline__ float fast_sqrtf(float x) {
    float r;
    asm("sqrt.approx.f32 %0, %1;" : "=f"(r) : "f"(x));
    return r;
}

// jax top_k total order: smaller cost wins; exact tie -> smaller query index.
__device__ __forceinline__ bool better(float va, int ia, float vb, int ib) {
    return (va < vb) || (va == vb && ia < ib);
}

// Generation barrier. Arrival = one RMW/block; POLLING = volatile loads only
// (L2 reads don't serialize like RMWs -> release visible fast).
// Returns the new generation value (uniform across all blocks).
__device__ __forceinline__ unsigned grid_barrier() {
    __shared__ unsigned sgen;
    __syncthreads();
    if (threadIdx.x == 0) {
        unsigned gen = *(volatile unsigned*)&g_bar_gen;  // read BEFORE arriving
        __threadfence();
        if (atomicAdd(&g_bar_arrive, 1u) == NBLOCKS - 1) {
            atomicExch(&g_bar_arrive, 0u);
            __threadfence();
            atomicAdd(&g_bar_gen, 1u);
        } else {
            while (*(volatile unsigned*)&g_bar_gen == gen) __nanosleep(128);
        }
        __threadfence();
        sgen = gen + 1;
    }
    __syncthreads();
    return sgen;
}

__device__ __forceinline__ float block_reduce_256(float v) {
    __shared__ float ws[8];
    __syncthreads();                        // protect ws across repeated calls
#pragma unroll
    for (int off = 16; off; off >>= 1) v += __shfl_xor_sync(0xffffffffu, v, off);
    if ((threadIdx.x & 31) == 0) ws[threadIdx.x >> 5] = v;
    __syncthreads();
    float t = 0.0f;
    if (threadIdx.x < 8) {
        t = ws[threadIdx.x];
#pragma unroll
        for (int off = 4; off; off >>= 1) t += __shfl_xor_sync(0xffu, t, off);
    }
    return t;   // valid in thread 0
}

// Identical code in phases A and C -> identical bins (required for scatter).
struct QP { float p0, p1, nll1, key; int bin; };
__device__ __forceinline__ QP qprob(const float* __restrict__ pl, int i, int lab) {
    float l0 = pl[2 * i], l1 = pl[2 * i + 1];
    float m  = fmaxf(l0, l1);
    float e0 = __expf(l0 - m), e1 = __expf(l1 - m);
    float sum = e0 + e1, inv = 1.0f / sum;
    QP r;
    r.p0 = e0 * inv; r.p1 = e1 * inv;
    r.nll1 = m + __logf(sum) - l1;
    r.key = lab ? fmaxf(r.p0, r.p1) : r.p0;   // lower bound on p_label
    r.bin = min(NBINS - 1, (int)(r.key * 256.0f));
    return r;
}

#define CEX3(va, ia, sa, vb, ib, sb)                                   \
    if (better(vb, ib, va, ia)) {                                      \
        float tv = va; va = vb; vb = tv;                               \
        int ti = ia; ia = ib; ib = ti;                                 \
        int ts = sa; sa = sb; sb = ts;                                 \
    }

#define INS(cst, qi, ps)                                                      \
    if (better(cst, qi, v3, i3)) {                                            \
        if (better(cst, qi, v1, i1)) {                                        \
            v3 = v2; i3 = i2; s3 = s2; v2 = v1; i2 = i1; s2 = s1;             \
            if (better(cst, qi, v0, i0)) {                                    \
                v1 = v0; i1 = i0; s1 = s0; v0 = cst; i0 = qi; s0 = ps;        \
            } else { v1 = cst; i1 = qi; s1 = ps; }                            \
        } else if (better(cst, qi, v2, i2)) {                                 \
            v3 = v2; i3 = i2; s3 = s2; v2 = cst; i2 = qi; s2 = ps;            \
        } else { v3 = cst; i3 = qi; s3 = ps; }                                \
    }

__global__ __launch_bounds__(NTHREADS, 4) void k_all(
    const float* __restrict__ pc, const float* __restrict__ pl,
    const float* __restrict__ gtc, const int* __restrict__ gtl,
    const unsigned char* __restrict__ gmsk, float* __restrict__ out)
{
    __shared__ union { unsigned u[NCHUNK]; float f[NCHUNK]; } sm;   // 2 KB
    __shared__ unsigned sbase[NBINS];  // per-batch descending bases (phase C)
    __shared__ unsigned h2[NBINS];     // claimed scatter bases (phase C)
    __shared__ int slabA;              // own batch "any label != 0" (loose)
    __shared__ int slast;
    const int tid  = threadIdx.x;
    const int bA = blockIdx.x >> 6;             // 64 blocks per batch
    const int iA = blockIdx.x * NTHREADS + tid; // this thread's item
    const float PINF = __int_as_float(0x7f800000);
    const float NINF = __int_as_float(0xff800000);

    // Loose label flag for OWN batch only (4 loads/thread).
    if (tid == 0) slabA = 0;
    __syncthreads();
#pragma unroll
    for (int k = 0; k < 4; k++)
        if (gtl[bA * NG + tid + k * 256] != 0) slabA = 1;  // benign race
    __syncthreads();

    // ================= Phase A: compact (block 0) + softmax/smem-hist =======
    if (blockIdx.x == 0) {
        if (tid == 0) {
            bool any_mis = false, b1nz = false, any3f = false;
            for (int t = 0; t < 256; t++) {
                unsigned char v = gmsk[t];
                if ((t & 3) != 0 && v) {
                    any_mis = true;
                    if ((t & 3) == 1) b1nz = true;
                    if (v == 0x3F) any3f = true;
                }
            }
            g_mask_kind = !any_mis ? 0 : ((!b1nz && any3f) ? 2 : 1);
        }
        __syncthreads();
        int b = tid >> 5, lane = tid & 31, kind = g_mask_kind;
        int cnt = 0, labnz = 0;
        for (int j = 0; j < NG; j += 32) {
            int g = j + lane, i = b * NG + g;
            bool mk;
            if (kind == 0)      mk = ((const int*)gmsk)[i] != 0;
            else if (kind == 1) mk = gmsk[i] != 0;
            else                mk = ((const float*)gmsk)[i] != 0.0f;
            unsigned bal = __ballot_sync(0xffffffffu, mk);
            if (mk) {
                int pos = cnt + __popc(bal & ((1u << lane) - 1u));
                g_valid_list[b][pos] = g;
                if (gtl[i] != 0) labnz = 1;
            }
            cnt += __popc(bal);
        }
        unsigned lb = __ballot_sync(0xffffffffu, labnz);
        if (lane == 0) { g_valid_cnt[b] = cnt; g_lab_nz[b] = (lb != 0); }
    }
    sm.u[tid] = 0u;
    __syncthreads();
    float cls1;
    {
        QP q = qprob(pl, iA, slabA);
        atomicAdd(&sm.u[q.bin], 1u);          // smem histogram
        cls1 = q.nll1;
    }
    __syncthreads();
    if (sm.u[tid]) atomicAdd(&g_hist[bA * NBINS + tid], sm.u[tid]);
    {
        float p = block_reduce_256(cls1);
        if (tid == 0) atomicAdd(&g_cls1, p);
    }
    grid_barrier();                        // hist complete

    // ====== Phase C: redundant per-block bases + two-pass block scatter =====
    {
        unsigned h0 = g_hist[bA * NBINS + tid];
        sm.u[tid] = h0;
        __syncthreads();
        for (int off = 1; off < NBINS; off <<= 1) {
            unsigned v = (tid + off < NBINS) ? sm.u[tid + off] : 0u;
            __syncthreads();
            sm.u[tid] += v;
            __syncthreads();
        }
        sbase[tid] = sm.u[tid] - h0;       // items in bins ABOVE tid
        __syncthreads();

        int labS = g_lab_nz[bA];
        QP q = qprob(pl, iA, slabA);
        float x = pc[2 * iA], y = pc[2 * iA + 1];
        sm.u[tid] = 0u;
        __syncthreads();
        atomicAdd(&sm.u[q.bin], 1u);
        __syncthreads();
        unsigned cb_ = sm.u[tid];
        h2[tid] = sbase[tid] +
                  (cb_ ? atomicAdd(&g_cursor[bA * NBINS + tid], cb_) : 0u);
        __syncthreads();
        sm.u[tid] = 0u;
        __syncthreads();
        int qi = iA & (NQ - 1);
        unsigned r = atomicAdd(&sm.u[q.bin], 1u);
        unsigned pos = h2[q.bin] + r;
        g_sq[bA * NQ + pos] = make_float4(x, y, -q.p0, __int_as_float(qi));
        // raw-uint max == float min (keys strictly negative)
        atomicMax(&g_chunkU[bA * NCHUNK + (pos >> 5)], __float_as_uint(-q.key));
        if (labS) g_sp1[bA * NQ + pos] = -q.p1;
    }
    unsigned tag = grid_barrier();         // scatter complete; tag = run gen

    // ================= Phase D: split top-4 per gt ==========================
    // block = (batch[3b], part[6b]); parts 0..15 cover 1024 slots/batch,
    // parts >=16 skip uniformly. Lane = gt(8) x split(4).
    float v0 = PINF, v1 = PINF, v2 = PINF, v3 = NINF;
    int i0 = 0x7fffffff, i1 = 0x7fffffff, i2 = 0x7fffffff, i3 = 0x7fffffff;
    int s0 = 0, s1 = 0, s2 = 0, s3 = 0;
    bool leader = false;
    float gx = 0.0f, gy = 0.0f;

    {
        int part = blockIdx.x & 63;
        int cnt = g_valid_cnt[bA];
        if (part * 64 < cnt) {                     // block-uniform
            sm.f[tid]       = __uint_as_float(g_chunkU[bA * NCHUNK + tid]);
            sm.f[tid + 256] = __uint_as_float(g_chunkU[bA * NCHUNK + tid + 256]);
            __syncthreads();
            for (int off = 1; off < NCHUNK; off <<= 1) {
                float a  = (tid + off < NCHUNK) ? sm.f[tid + off] : PINF;
                float b2 = (tid + 256 + off < NCHUNK) ? sm.f[tid + 256 + off] : PINF;
                __syncthreads();
                sm.f[tid]       = fminf(sm.f[tid], a);
                sm.f[tid + 256] = fminf(sm.f[tid + 256], b2);
                __syncthreads();
            }

            int w = tid >> 5, lane = tid & 31;
            int g = lane >> 2, s = lane & 3;
            int slot = part * 64 + w * 8 + g;
            bool act = slot < cnt;
            leader = act && (s == 0);
            int gi = g_valid_list[bA][act ? slot : 0];
            gx = gtc[(bA * NG + gi) * 2];
            gy = gtc[(bA * NG + gi) * 2 + 1];
            bool lab0 = (gtl[bA * NG + gi] == 0);
            if (act) v3 = PINF;                     // inactive: v3=-inf -> break

            const float4* __restrict__ qb = g_sq + bA * NQ;
            if (!g_lab_nz[bA]) {
                for (int c = s; c < NCHUNK; c += 4) {
                    if (sm.f[c] > v3) break;
                    int cb = c * 32;
#pragma unroll 4
                    for (int jj = 0; jj < 32; jj++) {
                        float4 q = qb[cb + jj];
                        float dx = q.x - gx, dy = q.y - gy;
                        float cst = fmaf(0.1f, fast_sqrtf(fmaf(dx, dx, dy * dy)), q.z);
                        if (cst <= v3) { int qi = __float_as_int(q.w); int ps = cb + jj; INS(cst, qi, ps); }
                    }
                }
            } else {
                const float* __restrict__ z1 = g_sp1 + bA * NQ;
                for (int c = s; c < NCHUNK; c += 4) {
                    if (sm.f[c] > v3) break;
                    int cb = c * 32;
                    for (int jj = 0; jj < 32; jj++) {
                        float4 q = qb[cb + jj];
                        float zc = lab0 ? q.z : z1[cb + jj];
                        float dx = q.x - gx, dy = q.y - gy;
                        float cst = fmaf(0.1f, fast_sqrtf(fmaf(dx, dx, dy * dy)), zc);
                        if (cst <= v3) { int qi = __float_as_int(q.w); int ps = cb + jj; INS(cst, qi, ps); }
                    }
                }
            }

            // Merge the 4 disjoint split lists per gt (xor 2, then 1).
#pragma unroll
            for (int off = 2; off >= 1; off >>= 1) {
                float w0 = __shfl_xor_sync(0xffffffffu, v0, off);
                float w1 = __shfl_xor_sync(0xffffffffu, v1, off);
                float w2 = __shfl_xor_sync(0xffffffffu, v2, off);
                float w3 = __shfl_xor_sync(0xffffffffu, v3, off);
                int j0 = __shfl_xor_sync(0xffffffffu, i0, off);
                int j1 = __shfl_xor_sync(0xffffffffu, i1, off);
                int j2 = __shfl_xor_sync(0xffffffffu, i2, off);
                int j3 = __shfl_xor_sync(0xffffffffu, i3, off);
                int t0 = __shfl_xor_sync(0xffffffffu, s0, off);
                int t1 = __shfl_xor_sync(0xffffffffu, s1, off);
                int t2 = __shfl_xor_sync(0xffffffffu, s2, off);
                int t3 = __shfl_xor_sync(0xffffffffu, s3, off);
                // lower half of bitonic merge-8
                if (better(w3, j3, v0, i0)) { v0 = w3; i0 = j3; s0 = t3; }
                if (better(w2, j2, v1, i1)) { v1 = w2; i1 = j2; s1 = t2; }
                if (better(w1, j1, v2, i2)) { v2 = w1; i2 = j1; s2 = t1; }
                if (better(w0, j0, v3, i3)) { v3 = w0; i3 = j0; s3 = t0; }
                // cleanup sort-4
                CEX3(v0, i0, s0, v2, i2, s2);
                CEX3(v1, i1, s1, v3, i3, s3);
                CEX3(v0, i0, s0, v1, i1, s1);
                CEX3(v2, i2, s2, v3, i3, s3);
            }
        }
    }

    // Epilogue: reg partial + gen-tagged match dedup + cls correction.
    float regs_ = 0.0f, corr = 0.0f;
    if (leader) {
        int ps4[4] = {s0, s1, s2, s3};
        int ii4[4] = {i0, i1, i2, i3};
        const float4* __restrict__ qb = g_sq + bA * NQ;
#pragma unroll
        for (int k = 0; k < 4; k++) {
            float4 q = qb[ps4[k]];
            float dx = q.x - gx, dy = q.y - gy;
            regs_ += dx * dx + dy * dy;
            int gidx = bA * NQ + ii4[k];
            if (atomicExch(&g_match[gidx], tag) != tag)  // first matcher pays
                corr += pl[2 * gidx + 1] - pl[2 * gidx];
        }
    }
    {
        float rsum = block_reduce_256(regs_);
        float csum = block_reduce_256(corr);
        if (tid == 0) {
            if (rsum != 0.0f) atomicAdd(&g_reg, rsum);
            if (csum != 0.0f) atomicAdd(&g_cls2, csum);
        }
    }

    // ============ Completion: fence + done-counter; last block finishes =====
    __threadfence();
    __syncthreads();
    if (tid == 0) {
        unsigned t = atomicAdd(&g_done, 1u);
        slast = (t == NBLOCKS - 1);
    }
    __syncthreads();
    if (slast) {
        for (int j = tid; j < BS * NBINS; j += NTHREADS) {
            g_hist[j] = 0u;
            g_cursor[j] = 0u;
        }
        for (int j = tid; j < BS * NCHUNK; j += NTHREADS) g_chunkU[j] = 0u;
        if (tid == 0) {
            float R = atomicAdd(&g_reg, 0.0f);
            float A = atomicAdd(&g_cls1, 0.0f) + atomicAdd(&g_cls2, 0.0f);
            int n = 0;
#pragma unroll
            for (int b = 0; b < BS; b++) n += g_valid_cnt[b];
            float denom = 8.0f * (float)(n > 0 ? n : 1);   // n_valid*TOP_K*2
            out[0] = 5.0f * R / denom;
            out[1] = A / (float)(BS * NQ);
            g_reg = 0.0f; g_cls1 = 0.0f; g_cls2 = 0.0f;
            atomicExch(&g_done, 0u);
        }
    }
}

extern "C" void kernel_launch(void* const* d_in, const int* in_sizes, int n_in,
                              void* d_out, int out_size) {
    const float* pc   = (const float*)d_in[0];   // pred_coords (8,16384,2)
    const float* pl   = (const float*)d_in[1];   // pred_logits (8,16384,2)
    const float* gtc  = (const float*)d_in[2];   // gt_coords   (8,1024,2)
    const int*   gtl  = (const int*)d_in[3];     // gt_labels   (8,1024)
    const unsigned char* gmsk = (const unsigned char*)d_in[4];  // gt_masks

    k_all<<<NBLOCKS, NTHREADS>>>(pc, pl, gtc, gtl, gmsk, (float*)d_out);
}